// round 1
// baseline (speedup 1.0000x reference)
#include <cuda_runtime.h>
#include <math.h>

// Router kernel: logits = H[T,D] @ W[E,D]^T, affine-calibrate, fp32 softmax,
// top-8 (stable, lowest-index tie-break like jax.lax.top_k).
// Output packing assumption: d_out = probs[T*E] || topk_w[T*8] || topk_idx(as float)[T*8]

#define TM 64      // tokens per block
#define TN 64      // experts (== E)
#define KT 16      // K tile
#define NT 128     // threads per block
#define TOPK 8

__global__ __launch_bounds__(NT)
void router_kernel(const float* __restrict__ A,        // [T, D]
                   const float* __restrict__ W,        // [E, D]
                   const float* __restrict__ cal_scale,// [E]
                   const float* __restrict__ cal_bias, // [E]
                   float* __restrict__ out_probs,      // [T, E]
                   float* __restrict__ out_wts,        // [T, 8]
                   float* __restrict__ out_idx,        // [T, 8] (float-cast indices)
                   int D)
{
    __shared__ float As[2][KT][TM];
    __shared__ float Bs[2][KT][TN];
    __shared__ float lg[TM][TN + 1];   // +1 pad: conflict-free per-token rows

    const int tid = threadIdx.x;
    const int m0  = blockIdx.x * TM;

    // compute-thread tile: 16 (m) x 8 (n) threads, each 4 tokens x 8 experts
    const int tm = tid >> 3;    // 0..15
    const int tn = tid & 7;     // 0..7

    // load mapping: 64 rows x 4 float4 columns per tile, 2 rows per thread
    const int r0 = tid >> 2;          // 0..31
    const int c0 = (tid & 3) * 4;     // float offset of this thread's float4
    const int r1 = r0 + 32;

    const float* Ab = A + (size_t)m0 * D;

    float acc[4][8];
#pragma unroll
    for (int i = 0; i < 4; ++i)
#pragma unroll
        for (int j = 0; j < 8; ++j) acc[i][j] = 0.f;

    const int ntiles = D / KT;

    // ---- prologue: tile 0 ----
    {
        float4 a0 = *reinterpret_cast<const float4*>(Ab + (size_t)r0 * D + c0);
        float4 a1 = *reinterpret_cast<const float4*>(Ab + (size_t)r1 * D + c0);
        float4 b0 = *reinterpret_cast<const float4*>(W  + (size_t)r0 * D + c0);
        float4 b1 = *reinterpret_cast<const float4*>(W  + (size_t)r1 * D + c0);
#pragma unroll
        for (int u = 0; u < 4; ++u) {
            As[0][c0 + u][r0] = ((const float*)&a0)[u];
            As[0][c0 + u][r1] = ((const float*)&a1)[u];
            Bs[0][c0 + u][r0] = ((const float*)&b0)[u];
            Bs[0][c0 + u][r1] = ((const float*)&b1)[u];
        }
    }
    __syncthreads();

    // ---- main loop: double-buffered, prefetch next tile into registers ----
    int buf = 0;
    for (int t = 0; t < ntiles; ++t) {
        float4 na0, na1, nb0, nb1;
        const bool have_next = (t + 1 < ntiles);
        if (have_next) {
            const int kt = (t + 1) * KT;
            na0 = *reinterpret_cast<const float4*>(Ab + (size_t)r0 * D + kt + c0);
            na1 = *reinterpret_cast<const float4*>(Ab + (size_t)r1 * D + kt + c0);
            nb0 = *reinterpret_cast<const float4*>(W  + (size_t)r0 * D + kt + c0);
            nb1 = *reinterpret_cast<const float4*>(W  + (size_t)r1 * D + kt + c0);
        }

        const float (*Ac)[TM] = As[buf];
        const float (*Bc)[TN] = Bs[buf];
#pragma unroll
        for (int k = 0; k < KT; ++k) {
            float4 av  = *reinterpret_cast<const float4*>(&Ac[k][tm * 4]);
            float4 bv0 = *reinterpret_cast<const float4*>(&Bc[k][tn * 8]);
            float4 bv1 = *reinterpret_cast<const float4*>(&Bc[k][tn * 8 + 4]);
            const float* ap  = (const float*)&av;
            const float* bp0 = (const float*)&bv0;
            const float* bp1 = (const float*)&bv1;
#pragma unroll
            for (int i = 0; i < 4; ++i) {
#pragma unroll
                for (int j = 0; j < 4; ++j) {
                    acc[i][j]     = fmaf(ap[i], bp0[j], acc[i][j]);
                    acc[i][j + 4] = fmaf(ap[i], bp1[j], acc[i][j + 4]);
                }
            }
        }

        if (have_next) {
            const int nb = buf ^ 1;
#pragma unroll
            for (int u = 0; u < 4; ++u) {
                As[nb][c0 + u][r0] = ((const float*)&na0)[u];
                As[nb][c0 + u][r1] = ((const float*)&na1)[u];
                Bs[nb][c0 + u][r0] = ((const float*)&nb0)[u];
                Bs[nb][c0 + u][r1] = ((const float*)&nb1)[u];
            }
        }
        __syncthreads();
        buf ^= 1;
    }

    // ---- epilogue: calibrated logits -> shared ----
#pragma unroll
    for (int j = 0; j < 8; ++j) {
        const int e = tn * 8 + j;
        const float s = __ldg(cal_scale + e);
        const float b = __ldg(cal_bias + e);
#pragma unroll
        for (int i = 0; i < 4; ++i) {
            lg[tm * 4 + i][e] = fmaf(acc[i][j], s, b);
        }
    }
    __syncthreads();

    // fp32 softmax, one thread per token (rows padded to 65 -> no bank conflicts)
    if (tid < TM) {
        float* row = lg[tid];
        float mx = row[0];
        for (int e = 1; e < TN; ++e) mx = fmaxf(mx, row[e]);
        float sum = 0.f;
        for (int e = 0; e < TN; ++e) { float p = expf(row[e] - mx); row[e] = p; sum += p; }
        const float inv = 1.f / sum;
        for (int e = 0; e < TN; ++e) row[e] *= inv;
    }
    __syncthreads();

    // coalesced probs store
    {
        float* dst = out_probs + (size_t)m0 * TN;
        for (int idx = tid; idx < TM * TN; idx += NT) {
            dst[idx] = lg[idx >> 6][idx & 63];
        }
    }
    __syncthreads();

    // top-8 per token: 8 passes of stable argmax (strict > keeps lowest index,
    // matching jax.lax.top_k tie-break); probs >= 0 so -1 is a safe sentinel.
    if (tid < TM) {
        float* row = lg[tid];
        const size_t token = (size_t)m0 + tid;
        for (int kk = 0; kk < TOPK; ++kk) {
            float best = -1.f; int bi = 0;
            for (int e = 0; e < TN; ++e) {
                if (row[e] > best) { best = row[e]; bi = e; }
            }
            out_wts[token * TOPK + kk] = best;
            out_idx[token * TOPK + kk] = (float)bi;
            row[bi] = -1.f;
        }
    }
}

extern "C" void kernel_launch(void* const* d_in, const int* in_sizes, int n_in,
                              void* d_out, int out_size)
{
    const float* h  = (const float*)d_in[0];   // hidden_states [B,S,D] fp32
    const float* W  = (const float*)d_in[1];   // router_weight [E,D] fp32
    const float* sc = (const float*)d_in[2];   // cal_scale [E]
    const float* bi = (const float*)d_in[3];   // cal_bias  [E]

    const int E = in_sizes[2];                 // 64
    const int D = in_sizes[1] / E;             // 2048
    const int T = in_sizes[0] / D;             // 16384

    float* probs = (float*)d_out;
    float* wts   = probs + (size_t)T * E;
    float* idxf  = wts   + (size_t)T * TOPK;

    dim3 grid(T / TM);
    router_kernel<<<grid, NT>>>(h, W, sc, bi, probs, wts, idxf, D);
}